// round 1
// baseline (speedup 1.0000x reference)
#include <cuda_runtime.h>
#include <cuda_bf16.h>
#include <mma.h>

using namespace nvcuda;
typedef __nv_bfloat16 bf16;

#define BATCH 8192
#define NCLUS 4096
#define DIM   3072
#define BK    32
#define LDA   40      // BK + 8 pad (bf16 elems); row stride 80B = 5*16B -> uint4 aligned
#define LDB2  136     // 128 + 8 pad; row stride 272B = 17*16B

// ---- device scratch (allocation-free contract: __device__ globals) ----
__device__ bf16  g_Xb[(size_t)BATCH * DIM];   // x in bf16
__device__ bf16  g_Mb[(size_t)NCLUS * DIM];   // means in bf16 (unscaled)
__device__ float g_xsq[BATCH];                // ||x_m||^2
__device__ float g_msq[NCLUS];                // ||mean_n||^2
__device__ float g_S [(size_t)BATCH * NCLUS]; // logits
__device__ bf16  g_P [(size_t)BATCH * NCLUS]; // softmax weights (bf16)

// ---------------------------------------------------------------------
// Convert fp32 rows -> bf16, and compute per-row sum of squares.
// which==0: x -> g_Xb/g_xsq ; which==1: means -> g_Mb/g_msq
// ---------------------------------------------------------------------
__global__ __launch_bounds__(256) void convert_rows(const float* __restrict__ src, int which)
{
    bf16*  dst = which ? g_Mb  : g_Xb;
    float* sq  = which ? g_msq : g_xsq;
    const int row = blockIdx.x;
    const int tid = threadIdx.x;

    const float4* s4 = reinterpret_cast<const float4*>(src + (size_t)row * DIM);
    uint2* d2p       = reinterpret_cast<uint2*>(dst + (size_t)row * DIM);

    float ss = 0.f;
    for (int i = tid; i < DIM / 4; i += 256) {
        float4 v = s4[i];
        ss += v.x*v.x + v.y*v.y + v.z*v.z + v.w*v.w;
        __nv_bfloat162 lo = __floats2bfloat162_rn(v.x, v.y);
        __nv_bfloat162 hi = __floats2bfloat162_rn(v.z, v.w);
        uint2 u;
        u.x = *reinterpret_cast<unsigned int*>(&lo);
        u.y = *reinterpret_cast<unsigned int*>(&hi);
        d2p[i] = u;
    }
    __shared__ float red[256];
    red[tid] = ss;
    __syncthreads();
    #pragma unroll
    for (int s = 128; s > 0; s >>= 1) {
        if (tid < s) red[tid] += red[tid + s];
        __syncthreads();
    }
    if (tid == 0) sq[row] = red[0];
}

// ---------------------------------------------------------------------
// GEMM1 (NT): dot[m,n] = x_m . mean_n  ->  logits into g_S
// logits = -0.5 * max(xsq[m] + scale^2*msq[n] - 2*scale*dot, 0) / var_t
// Tiles: 128x128x32, 8 warps (4 x 2), warp tile 32x64, wmma 16x16x16 bf16.
// ---------------------------------------------------------------------
__global__ __launch_bounds__(256, 1) void gemm_logits(const float* __restrict__ tptr,
                                                      const float* __restrict__ sdptr)
{
    const int m0  = blockIdx.y * 128;
    const int n0  = blockIdx.x * 128;
    const int tid = threadIdx.x;
    const int wid = tid >> 5, lane = tid & 31;
    const int wm  = wid >> 1, wn = wid & 1;   // 4 x 2 warp grid

    __shared__ __align__(16) bf16 sA[2][128][LDA];
    __shared__ __align__(16) bf16 sB[2][128][LDA];

    wmma::fragment<wmma::accumulator, 16, 16, 16, float> acc[2][4];
    #pragma unroll
    for (int i = 0; i < 2; i++)
        #pragma unroll
        for (int j = 0; j < 4; j++) wmma::fill_fragment(acc[i][j], 0.0f);

    const int K  = DIM;
    const int nk = K / BK;   // 96

    // preload tile 0
    #pragma unroll
    for (int it = 0; it < 2; it++) {
        int e = tid + it * 256;
        int r = e >> 2, c8 = (e & 3) << 3;
        *reinterpret_cast<uint4*>(&sA[0][r][c8]) =
            *reinterpret_cast<const uint4*>(&g_Xb[(size_t)(m0 + r) * K + c8]);
        *reinterpret_cast<uint4*>(&sB[0][r][c8]) =
            *reinterpret_cast<const uint4*>(&g_Mb[(size_t)(n0 + r) * K + c8]);
    }
    __syncthreads();

    for (int kt = 0; kt < nk; kt++) {
        const int cur = kt & 1;
        uint4 pa[2], pb[2];
        if (kt + 1 < nk) {
            #pragma unroll
            for (int it = 0; it < 2; it++) {
                int e = tid + it * 256;
                int r = e >> 2, c8 = (e & 3) << 3;
                pa[it] = *reinterpret_cast<const uint4*>(&g_Xb[(size_t)(m0 + r) * K + (kt + 1) * BK + c8]);
                pb[it] = *reinterpret_cast<const uint4*>(&g_Mb[(size_t)(n0 + r) * K + (kt + 1) * BK + c8]);
            }
        }
        #pragma unroll
        for (int ks = 0; ks < 2; ks++) {
            wmma::fragment<wmma::matrix_a, 16, 16, 16, bf16, wmma::row_major> af[2];
            wmma::fragment<wmma::matrix_b, 16, 16, 16, bf16, wmma::col_major> bfr[4];
            #pragma unroll
            for (int i = 0; i < 2; i++)
                wmma::load_matrix_sync(af[i], &sA[cur][wm * 32 + i * 16][ks * 16], LDA);
            #pragma unroll
            for (int j = 0; j < 4; j++)
                wmma::load_matrix_sync(bfr[j], &sB[cur][wn * 64 + j * 16][ks * 16], LDA);
            #pragma unroll
            for (int i = 0; i < 2; i++)
                #pragma unroll
                for (int j = 0; j < 4; j++)
                    wmma::mma_sync(acc[i][j], af[i], bfr[j], acc[i][j]);
        }
        if (kt + 1 < nk) {
            #pragma unroll
            for (int it = 0; it < 2; it++) {
                int e = tid + it * 256;
                int r = e >> 2, c8 = (e & 3) << 3;
                *reinterpret_cast<uint4*>(&sA[cur ^ 1][r][c8]) = pa[it];
                *reinterpret_cast<uint4*>(&sB[cur ^ 1][r][c8]) = pb[it];
            }
        }
        __syncthreads();
    }

    // epilogue: fuse bias + clamp + scale
    const float scale  = expf(-tptr[0]);
    const float s2     = scale * scale;
    const float sdv    = sdptr[0];
    const float var_t  = s2 * sdv * sdv + (1.0f - s2);
    const float halfiv = 0.5f / var_t;

    float* stage = reinterpret_cast<float*>(&sA[0][0][0]) + wid * 256;  // smem reuse (post-barrier)
    #pragma unroll
    for (int i = 0; i < 2; i++) {
        #pragma unroll
        for (int j = 0; j < 4; j++) {
            wmma::store_matrix_sync(stage, acc[i][j], 16, wmma::mem_row_major);
            __syncwarp();
            const int mb = m0 + wm * 32 + i * 16;
            const int nb = n0 + wn * 64 + j * 16;
            #pragma unroll
            for (int q = 0; q < 8; q++) {
                int idx = lane + q * 32;
                int r = idx >> 4, c = idx & 15;
                float dot = stage[idx];
                int m = mb + r, n = nb + c;
                float d2 = g_xsq[m] + s2 * g_msq[n] - 2.0f * scale * dot;
                d2 = fmaxf(d2, 0.0f);
                g_S[(size_t)m * NCLUS + n] = -d2 * halfiv;
            }
            __syncwarp();
        }
    }
}

// ---------------------------------------------------------------------
// Row softmax over g_S (4096 cols) -> g_P (bf16 normalized weights)
// ---------------------------------------------------------------------
__global__ __launch_bounds__(256) void softmax_rows()
{
    const int row = blockIdx.x;
    const int tid = threadIdx.x;
    const float* Sr = g_S + (size_t)row * NCLUS;

    float v[16];
    float mx = -3.4e38f;
    #pragma unroll
    for (int i = 0; i < 16; i++) {
        v[i] = Sr[tid + i * 256];
        mx = fmaxf(mx, v[i]);
    }
    __shared__ float red[256];
    red[tid] = mx;
    __syncthreads();
    #pragma unroll
    for (int s = 128; s > 0; s >>= 1) {
        if (tid < s) red[tid] = fmaxf(red[tid], red[tid + s]);
        __syncthreads();
    }
    mx = red[0];
    __syncthreads();

    float sum = 0.f;
    #pragma unroll
    for (int i = 0; i < 16; i++) {
        v[i] = expf(v[i] - mx);
        sum += v[i];
    }
    red[tid] = sum;
    __syncthreads();
    #pragma unroll
    for (int s = 128; s > 0; s >>= 1) {
        if (tid < s) red[tid] += red[tid + s];
        __syncthreads();
    }
    const float inv = 1.0f / red[0];

    bf16* Pr = g_P + (size_t)row * NCLUS;
    #pragma unroll
    for (int i = 0; i < 16; i++)
        Pr[tid + i * 256] = __float2bfloat16(v[i] * inv);
}

// ---------------------------------------------------------------------
// GEMM2 (NN): ct[m,d] = sum_n P[m,n] * mean[n,d]; fused final blend.
// out = (dw * x + (1-dw)*scale*ct) / scale
// ---------------------------------------------------------------------
__global__ __launch_bounds__(256, 1) void gemm_out(const float* __restrict__ xin,
                                                   const float* __restrict__ tptr,
                                                   const float* __restrict__ sdptr,
                                                   float* __restrict__ out)
{
    const int m0  = blockIdx.y * 128;
    const int n0  = blockIdx.x * 128;     // over DIM
    const int tid = threadIdx.x;
    const int wid = tid >> 5, lane = tid & 31;
    const int wm  = wid >> 1, wn = wid & 1;

    __shared__ __align__(16) bf16 sA[2][128][LDA];   // P rows (k-major, k = cluster)
    __shared__ __align__(16) bf16 sB[2][BK][LDB2];   // mean rows k, cols d

    wmma::fragment<wmma::accumulator, 16, 16, 16, float> acc[2][4];
    #pragma unroll
    for (int i = 0; i < 2; i++)
        #pragma unroll
        for (int j = 0; j < 4; j++) wmma::fill_fragment(acc[i][j], 0.0f);

    const int K  = NCLUS;
    const int nk = K / BK;   // 128

    #pragma unroll
    for (int it = 0; it < 2; it++) {
        int e = tid + it * 256;
        {
            int r = e >> 2, c8 = (e & 3) << 3;
            *reinterpret_cast<uint4*>(&sA[0][r][c8]) =
                *reinterpret_cast<const uint4*>(&g_P[(size_t)(m0 + r) * K + c8]);
        }
        {
            int r = e >> 4, c8 = (e & 15) << 3;
            *reinterpret_cast<uint4*>(&sB[0][r][c8]) =
                *reinterpret_cast<const uint4*>(&g_Mb[(size_t)r * DIM + n0 + c8]);
        }
    }
    __syncthreads();

    for (int kt = 0; kt < nk; kt++) {
        const int cur = kt & 1;
        uint4 pa[2], pb[2];
        if (kt + 1 < nk) {
            #pragma unroll
            for (int it = 0; it < 2; it++) {
                int e = tid + it * 256;
                {
                    int r = e >> 2, c8 = (e & 3) << 3;
                    pa[it] = *reinterpret_cast<const uint4*>(&g_P[(size_t)(m0 + r) * K + (kt + 1) * BK + c8]);
                }
                {
                    int r = e >> 4, c8 = (e & 15) << 3;
                    pb[it] = *reinterpret_cast<const uint4*>(&g_Mb[(size_t)((kt + 1) * BK + r) * DIM + n0 + c8]);
                }
            }
        }
        #pragma unroll
        for (int ks = 0; ks < 2; ks++) {
            wmma::fragment<wmma::matrix_a, 16, 16, 16, bf16, wmma::row_major> af[2];
            wmma::fragment<wmma::matrix_b, 16, 16, 16, bf16, wmma::row_major> bfr[4];
            #pragma unroll
            for (int i = 0; i < 2; i++)
                wmma::load_matrix_sync(af[i], &sA[cur][wm * 32 + i * 16][ks * 16], LDA);
            #pragma unroll
            for (int j = 0; j < 4; j++)
                wmma::load_matrix_sync(bfr[j], &sB[cur][ks * 16][wn * 64 + j * 16], LDB2);
            #pragma unroll
            for (int i = 0; i < 2; i++)
                #pragma unroll
                for (int j = 0; j < 4; j++)
                    wmma::mma_sync(acc[i][j], af[i], bfr[j], acc[i][j]);
        }
        if (kt + 1 < nk) {
            #pragma unroll
            for (int it = 0; it < 2; it++) {
                int e = tid + it * 256;
                {
                    int r = e >> 2, c8 = (e & 3) << 3;
                    *reinterpret_cast<uint4*>(&sA[cur ^ 1][r][c8]) = pa[it];
                }
                {
                    int r = e >> 4, c8 = (e & 15) << 3;
                    *reinterpret_cast<uint4*>(&sB[cur ^ 1][r][c8]) = pb[it];
                }
            }
        }
        __syncthreads();
    }

    // epilogue: blend with original fp32 x
    const float scale = expf(-tptr[0]);
    const float s2    = scale * scale;
    const float sdv   = sdptr[0];
    const float var_t = s2 * sdv * sdv + (1.0f - s2);
    const float dw    = s2 * sdv * sdv / var_t;
    const float w2    = (1.0f - dw) * scale;   // ct computed on unscaled means
    const float isc   = 1.0f / scale;

    float* stage = reinterpret_cast<float*>(&sA[0][0][0]) + wid * 256;
    #pragma unroll
    for (int i = 0; i < 2; i++) {
        #pragma unroll
        for (int j = 0; j < 4; j++) {
            wmma::store_matrix_sync(stage, acc[i][j], 16, wmma::mem_row_major);
            __syncwarp();
            const int mb = m0 + wm * 32 + i * 16;
            const int nb = n0 + wn * 64 + j * 16;
            #pragma unroll
            for (int q = 0; q < 8; q++) {
                int idx = lane + q * 32;
                int r = idx >> 4, c = idx & 15;
                float dot = stage[idx];
                int m = mb + r, d = nb + c;
                out[(size_t)m * DIM + d] =
                    (dw * xin[(size_t)m * DIM + d] + w2 * dot) * isc;
            }
            __syncwarp();
        }
    }
}

// ---------------------------------------------------------------------
extern "C" void kernel_launch(void* const* d_in, const int* in_sizes, int n_in,
                              void* d_out, int out_size)
{
    const float* x = nullptr;
    const float* means = nullptr;
    const float* t = nullptr;
    const float* sd = nullptr;
    for (int i = 0; i < n_in; i++) {
        if (in_sizes[i] == BATCH * DIM)      x = (const float*)d_in[i];
        else if (in_sizes[i] == NCLUS * DIM) means = (const float*)d_in[i];
        else if (in_sizes[i] == 1) {
            if (!t) t = (const float*)d_in[i];
            else    sd = (const float*)d_in[i];
        }
    }
    float* out = (float*)d_out;

    convert_rows<<<BATCH, 256>>>(x, 0);
    convert_rows<<<NCLUS, 256>>>(means, 1);
    gemm_logits<<<dim3(NCLUS / 128, BATCH / 128), 256>>>(t, sd);
    softmax_rows<<<BATCH, 256>>>();
    gemm_out<<<dim3(DIM / 128, BATCH / 128), 256>>>(x, t, sd, out);
}

// round 3
// speedup vs baseline: 1.6942x; 1.6942x over previous
#include <cuda_runtime.h>
#include <cuda_bf16.h>
#include <cstdint>

typedef __nv_bfloat16 bf16;

#define BATCH 8192
#define NCLUS 4096
#define DIM   3072

// ---- device scratch (allocation-free contract: __device__ globals) ----
__device__ bf16  g_Xb [(size_t)BATCH * DIM];   // x bf16 (K-major)
__device__ bf16  g_Mb [(size_t)NCLUS * DIM];   // means bf16 (K-major, GEMM1 B)
__device__ bf16  g_MbT[(size_t)DIM * NCLUS];   // means^T bf16 (K-major, GEMM2 B)
__device__ float g_xsq[BATCH];
__device__ float g_msq[NCLUS];
__device__ float g_S [(size_t)BATCH * NCLUS];  // logits fp32
__device__ bf16  g_P [(size_t)BATCH * NCLUS];  // softmax weights bf16

// ============================ PTX helpers ============================
__device__ __forceinline__ uint32_t smem_u32(const void* p) {
    uint32_t a;
    asm("{ .reg .u64 t; cvta.to.shared.u64 t, %1; cvt.u32.u64 %0, t; }" : "=r"(a) : "l"(p));
    return a;
}
#define CP_ASYNC16(sa, ga) \
    asm volatile("cp.async.cg.shared.global [%0], [%1], 16;" :: "r"(sa), "l"(ga) : "memory")
#define CP_COMMIT()  asm volatile("cp.async.commit_group;" ::: "memory")
#define CP_WAIT1()   asm volatile("cp.async.wait_group 1;" ::: "memory")
#define SWZ(off) ((off) ^ (((off) >> 3) & 0x70))

#define LDSM_X4(r0, r1, r2, r3, addr) \
    asm volatile("ldmatrix.sync.aligned.m8n8.x4.shared.b16 {%0,%1,%2,%3}, [%4];" \
                 : "=r"(r0), "=r"(r1), "=r"(r2), "=r"(r3) : "r"(addr))

#define MMA16816(c0, c1, c2, c3, a0, a1, a2, a3, b0, b1) \
    asm volatile("mma.sync.aligned.m16n8k16.row.col.f32.bf16.bf16.f32 " \
                 "{%0,%1,%2,%3}, {%4,%5,%6,%7}, {%8,%9}, {%0,%1,%2,%3};" \
                 : "+f"(c0), "+f"(c1), "+f"(c2), "+f"(c3) \
                 : "r"(a0), "r"(a1), "r"(a2), "r"(a3), "r"(b0), "r"(b1))

// ============================ prep kernels ============================
__global__ __launch_bounds__(256) void convert_rows(const float* __restrict__ src, int which)
{
    bf16*  dst = which ? g_Mb  : g_Xb;
    float* sq  = which ? g_msq : g_xsq;
    const int row = blockIdx.x;
    const int tid = threadIdx.x;
    const float4* s4 = reinterpret_cast<const float4*>(src + (size_t)row * DIM);
    uint2* d2p = reinterpret_cast<uint2*>(dst + (size_t)row * DIM);
    float ss = 0.f;
    for (int i = tid; i < DIM / 4; i += 256) {
        float4 v = s4[i];
        ss += v.x*v.x + v.y*v.y + v.z*v.z + v.w*v.w;
        __nv_bfloat162 lo = __floats2bfloat162_rn(v.x, v.y);
        __nv_bfloat162 hi = __floats2bfloat162_rn(v.z, v.w);
        uint2 u;
        u.x = *reinterpret_cast<unsigned int*>(&lo);
        u.y = *reinterpret_cast<unsigned int*>(&hi);
        d2p[i] = u;
    }
    __shared__ float red[256];
    red[tid] = ss;
    __syncthreads();
    #pragma unroll
    for (int s = 128; s > 0; s >>= 1) { if (tid < s) red[tid] += red[tid + s]; __syncthreads(); }
    if (tid == 0) sq[row] = red[0];
}

__global__ __launch_bounds__(256) void transpose_means(const float* __restrict__ means)
{
    __shared__ float tile[32][33];
    const int nb = blockIdx.x * 32, db = blockIdx.y * 32;
    const int tx = threadIdx.x & 31, ty = threadIdx.x >> 5;
    #pragma unroll
    for (int i = ty; i < 32; i += 8)
        tile[i][tx] = means[(size_t)(nb + i) * DIM + db + tx];
    __syncthreads();
    #pragma unroll
    for (int i = ty; i < 32; i += 8)
        g_MbT[(size_t)(db + i) * NCLUS + nb + tx] = __float2bfloat16(tile[tx][i]);
}

// ============================ HMMA GEMM ============================
// C[m,n] = sum_k A[m,k] * B[n,k]      (A row-major MxK, B row-major NxK)
// MODE 0: A=g_Xb [B,DIM],  B=g_Mb [N,DIM],  epilogue -> g_S logits
// MODE 1: A=g_P [B,NCLUS], B=g_MbT[D,NCLUS], epilogue -> out blend
#define TM 128
#define TN 128
#define BK 64
#define STAGES 3
#define STAGE_BYTES (TM * 128 + TN * 128)   // 16KB A + 16KB B
#define SMEM_DYN (STAGES * STAGE_BYTES)

template<int MODE>
__global__ __launch_bounds__(256, 2) void gemm_hmma(const float* __restrict__ tptr,
                                                    const float* __restrict__ sdptr,
                                                    const float* __restrict__ xin,
                                                    float* __restrict__ out)
{
    constexpr int K  = (MODE == 0) ? DIM : NCLUS;
    constexpr int nk = K / BK;
    const bf16* __restrict__ Ag = (MODE == 0) ? g_Xb : g_P;
    const bf16* __restrict__ Bg = (MODE == 0) ? g_Mb : g_MbT;

    const int m0  = blockIdx.y * TM;
    const int n0  = blockIdx.x * TN;
    const int tid = threadIdx.x;
    const int wid = tid >> 5, lane = tid & 31;
    const int wm  = wid >> 2;          // 0..1  -> 64-row slab
    const int wn  = wid & 3;           // 0..3  -> 32-col slab

    extern __shared__ __align__(1024) char dynraw[];
    const uint32_t dyn = smem_u32(dynraw);

    __shared__ float s_xsq[TM];
    __shared__ float s_msq[TN];
    if (MODE == 0) {
        if (tid < TM) s_xsq[tid] = g_xsq[m0 + tid];
        else if (tid < TM + TN) s_msq[tid - TM] = g_msq[n0 + tid - TM];
    }

    // ---- tile loader: 8 cp.async per thread (4 for A, 4 for B) ----
    auto loadTile = [&](int st, int kt) {
        const uint32_t sa = dyn + st * STAGE_BYTES;
        const uint32_t sb = sa + TM * 128;
        const bf16* Ab = Ag + (size_t)m0 * K + kt * BK;
        const bf16* Bb = Bg + (size_t)n0 * K + kt * BK;
        #pragma unroll
        for (int i = 0; i < 4; i++) {
            int chunk = i * 256 + tid;                 // 1024 chunks of 16B
            int r = chunk >> 3, c16 = chunk & 7;
            CP_ASYNC16(sa + SWZ((uint32_t)chunk * 16), Ab + (size_t)r * K + c16 * 8);
        }
        #pragma unroll
        for (int i = 0; i < 4; i++) {
            int chunk = i * 256 + tid;
            int r = chunk >> 3, c16 = chunk & 7;
            CP_ASYNC16(sb + SWZ((uint32_t)chunk * 16), Bb + (size_t)r * K + c16 * 8);
        }
    };

    float acc[4][4][4];
    #pragma unroll
    for (int mi = 0; mi < 4; mi++)
        #pragma unroll
        for (int ni = 0; ni < 4; ni++)
            #pragma unroll
            for (int q = 0; q < 4; q++) acc[mi][ni][q] = 0.f;

    loadTile(0, 0); CP_COMMIT();
    loadTile(1, 1); CP_COMMIT();

    // ldmatrix lane geometry (byte offsets within tile rows of 128B)
    const int a_row  = wm * 64 + (lane & 15);     // + mi*16
    const int a_c16  = (lane >> 4);               // 0/1 -> k-halves
    const int b_row  = wn * 32 + ((lane >> 4) & 1) * 8 + (lane & 7);  // + pi*16
    const int b_c16  = (lane >> 3) & 1;

    for (int kt = 0; kt < nk; kt++) {
        CP_WAIT1();
        __syncthreads();
        if (kt + 2 < nk) loadTile((kt + 2) % STAGES, kt + 2);
        CP_COMMIT();

        const uint32_t sa = dyn + (kt % STAGES) * STAGE_BYTES;
        const uint32_t sb = sa + TM * 128;

        #pragma unroll
        for (int ks = 0; ks < 4; ks++) {
            uint32_t af[4][4];
            #pragma unroll
            for (int mi = 0; mi < 4; mi++) {
                uint32_t off = (uint32_t)(a_row + mi * 16) * 128 + ks * 32 + a_c16 * 16;
                LDSM_X4(af[mi][0], af[mi][1], af[mi][2], af[mi][3], sa + SWZ(off));
            }
            uint32_t bf[4][2];
            #pragma unroll
            for (int pi = 0; pi < 2; pi++) {
                uint32_t off = (uint32_t)(b_row + pi * 16) * 128 + ks * 32 + b_c16 * 16;
                LDSM_X4(bf[pi*2][0], bf[pi*2][1], bf[pi*2+1][0], bf[pi*2+1][1], sb + SWZ(off));
            }
            #pragma unroll
            for (int mi = 0; mi < 4; mi++)
                #pragma unroll
                for (int ni = 0; ni < 4; ni++)
                    MMA16816(acc[mi][ni][0], acc[mi][ni][1], acc[mi][ni][2], acc[mi][ni][3],
                             af[mi][0], af[mi][1], af[mi][2], af[mi][3],
                             bf[ni][0], bf[ni][1]);
        }
    }

    // ---- fused epilogue ----
    const float scale = expf(-tptr[0]);
    const float s2    = scale * scale;
    const float sdv   = sdptr[0];
    const float var_t = s2 * sdv * sdv + (1.0f - s2);
    const float halfiv = 0.5f / var_t;
    const float dw  = s2 * sdv * sdv / var_t;
    const float w2  = (1.0f - dw) * scale;
    const float isc = 1.0f / scale;

    const int g  = lane >> 2;            // 0..7
    const int tc = (lane & 3) * 2;       // 0,2,4,6

    #pragma unroll
    for (int mi = 0; mi < 4; mi++) {
        const int r0 = m0 + wm * 64 + mi * 16 + g;
        #pragma unroll
        for (int ni = 0; ni < 4; ni++) {
            const int c = n0 + wn * 32 + ni * 8 + tc;
            if (MODE == 0) {
                const float xs0 = s_xsq[r0 - m0], xs1 = s_xsq[r0 + 8 - m0];
                const float mq0 = s_msq[c - n0],  mq1 = s_msq[c + 1 - n0];
                float2 v0, v1;
                v0.x = -fmaxf(xs0 + s2 * mq0 - 2.f * scale * acc[mi][ni][0], 0.f) * halfiv;
                v0.y = -fmaxf(xs0 + s2 * mq1 - 2.f * scale * acc[mi][ni][1], 0.f) * halfiv;
                v1.x = -fmaxf(xs1 + s2 * mq0 - 2.f * scale * acc[mi][ni][2], 0.f) * halfiv;
                v1.y = -fmaxf(xs1 + s2 * mq1 - 2.f * scale * acc[mi][ni][3], 0.f) * halfiv;
                *reinterpret_cast<float2*>(g_S + (size_t)r0 * NCLUS + c) = v0;
                *reinterpret_cast<float2*>(g_S + (size_t)(r0 + 8) * NCLUS + c) = v1;
            } else {
                const float2 x0 = *reinterpret_cast<const float2*>(xin + (size_t)r0 * DIM + c);
                const float2 x1 = *reinterpret_cast<const float2*>(xin + (size_t)(r0 + 8) * DIM + c);
                float2 v0, v1;
                v0.x = (dw * x0.x + w2 * acc[mi][ni][0]) * isc;
                v0.y = (dw * x0.y + w2 * acc[mi][ni][1]) * isc;
                v1.x = (dw * x1.x + w2 * acc[mi][ni][2]) * isc;
                v1.y = (dw * x1.y + w2 * acc[mi][ni][3]) * isc;
                *reinterpret_cast<float2*>(out + (size_t)r0 * DIM + c) = v0;
                *reinterpret_cast<float2*>(out + (size_t)(r0 + 8) * DIM + c) = v1;
            }
        }
    }
}

// ============================ softmax ============================
__global__ __launch_bounds__(256) void softmax_rows()
{
    const int row = blockIdx.x;
    const int tid = threadIdx.x;
    const float* Sr = g_S + (size_t)row * NCLUS;
    float v[16];
    float mx = -3.4e38f;
    #pragma unroll
    for (int i = 0; i < 16; i++) { v[i] = Sr[tid + i * 256]; mx = fmaxf(mx, v[i]); }
    __shared__ float red[256];
    red[tid] = mx; __syncthreads();
    #pragma unroll
    for (int s = 128; s > 0; s >>= 1) { if (tid < s) red[tid] = fmaxf(red[tid], red[tid+s]); __syncthreads(); }
    mx = red[0]; __syncthreads();
    float sum = 0.f;
    #pragma unroll
    for (int i = 0; i < 16; i++) { v[i] = expf(v[i] - mx); sum += v[i]; }
    red[tid] = sum; __syncthreads();
    #pragma unroll
    for (int s = 128; s > 0; s >>= 1) { if (tid < s) red[tid] += red[tid+s]; __syncthreads(); }
    const float inv = 1.0f / red[0];
    bf16* Pr = g_P + (size_t)row * NCLUS;
    #pragma unroll
    for (int i = 0; i < 16; i++) Pr[tid + i * 256] = __float2bfloat16(v[i] * inv);
}

// ============================ launcher ============================
extern "C" void kernel_launch(void* const* d_in, const int* in_sizes, int n_in,
                              void* d_out, int out_size)
{
    const float* x = nullptr;
    const float* means = nullptr;
    const float* t = nullptr;
    const float* sd = nullptr;
    for (int i = 0; i < n_in; i++) {
        if (in_sizes[i] == BATCH * DIM)      x = (const float*)d_in[i];
        else if (in_sizes[i] == NCLUS * DIM) means = (const float*)d_in[i];
        else if (in_sizes[i] == 1) { if (!t) t = (const float*)d_in[i]; else sd = (const float*)d_in[i]; }
    }
    float* out = (float*)d_out;

    static int configured = 0;
    if (!configured) {
        cudaFuncSetAttribute(gemm_hmma<0>, cudaFuncAttributeMaxDynamicSharedMemorySize, SMEM_DYN);
        cudaFuncSetAttribute(gemm_hmma<1>, cudaFuncAttributeMaxDynamicSharedMemorySize, SMEM_DYN);
        configured = 1;
    }

    convert_rows<<<BATCH, 256>>>(x, 0);
    convert_rows<<<NCLUS, 256>>>(means, 1);
    transpose_means<<<dim3(NCLUS / 32, DIM / 32), 256>>>(means);

    gemm_hmma<0><<<dim3(NCLUS / TN, BATCH / TM), 256, SMEM_DYN>>>(t, sd, x, out);
    softmax_rows<<<BATCH, 256>>>();
    gemm_hmma<1><<<dim3(DIM / TN, BATCH / TM), 256, SMEM_DYN>>>(t, sd, x, out);
}